// round 9
// baseline (speedup 1.0000x reference)
#include <cuda_runtime.h>
#include <cuda_fp16.h>
#include <cstdint>

#define MAXN 50000
#define MAXE 800000
#define FIN 256
#define FH  64
#define FOUT 40
#define KSTEPS 10
#define SCAN_TPB 256
#define MAXBLK 256

// packed fp32x2 helpers (Blackwell dual fp32)
#define PACK2(out, lo, hi) asm("mov.b64 %0, {%1, %2};" : "=l"(out) : "f"(lo), "f"(hi))
#define UNPACK2(lo, hi, in) asm("mov.b64 {%0, %1}, %2;" : "=f"(lo), "=f"(hi) : "l"(in))
#define FMA2(d, a, b, c) asm("fma.rn.f32x2 %0, %1, %2, %3;" : "=l"(d) : "l"(a), "l"(b), "l"(c))

// ---------------- static device scratch ----------------
__device__ int      g_deg[MAXN];
__device__ float    g_dinv[MAXN];
__device__ int      g_ptr[MAXN + 1];
__device__ int      g_cursor[MAXN];
__device__ int      g_part[MAXBLK];
__device__ unsigned g_bar_count;     // persistent-kernel barrier
__device__ unsigned g_bar_gen;
__device__ __align__(16) int2    g_csr[MAXE];
// feature pairing: slot p of a node = features (2p, 2p+1)
__device__ __align__(16) float2  g_h0[MAXN * 32];
__device__ __align__(16) __half2 g_hA[MAXN * 32];
__device__ __align__(16) __half2 g_hB[MAXN * 32];

__device__ __forceinline__ int clampN(int v, int n) {
    v = v < 0 ? 0 : v;
    return v >= n ? n - 1 : v;
}

// ---------------- graph preprocessing ----------------
__global__ void init_kernel(int n) {
    int i = blockIdx.x * blockDim.x + threadIdx.x;
    if (i < n) { g_deg[i] = 1; g_cursor[i] = 0; }   // self loop
}

__global__ void hist_kernel(const int* __restrict__ ei, int E, int n) {
    int e = blockIdx.x * blockDim.x + threadIdx.x;
    if (e < E) atomicAdd(&g_deg[clampN(ei[E + e], n)], 1);
}

// scan stage A: per-block sums of (deg-1); also computes dinv
__global__ void scanA_kernel(int n) {
    int i = blockIdx.x * blockDim.x + threadIdx.x;
    int lane = threadIdx.x & 31, wid = threadIdx.x >> 5;
    __shared__ int ws[SCAN_TPB / 32];
    int d = (i < n) ? g_deg[i] : 1;
    if (i < n) g_dinv[i] = rsqrtf((float)d);
    int v = (i < n) ? (d - 1) : 0;
    #pragma unroll
    for (int o = 16; o > 0; o >>= 1) v += __shfl_down_sync(0xFFFFFFFFu, v, o);
    if (lane == 0) ws[wid] = v;
    __syncthreads();
    if (wid == 0) {
        int s = (lane < SCAN_TPB / 32) ? ws[lane] : 0;
        #pragma unroll
        for (int o = 16; o > 0; o >>= 1) s += __shfl_down_sync(0xFFFFFFFFu, s, o);
        if (lane == 0) g_part[blockIdx.x] = s;
    }
}

// scan stage B: exclusive scan of block partials (single block)
__global__ void scanB_kernel(int nblocks, int n) {
    int tid = threadIdx.x, lane = tid & 31, wid = tid >> 5;
    __shared__ int ws[8];
    int v = (tid < nblocks) ? g_part[tid] : 0;
    int x = v;
    #pragma unroll
    for (int o = 1; o < 32; o <<= 1) {
        int y = __shfl_up_sync(0xFFFFFFFFu, x, o);
        if (lane >= o) x += y;
    }
    if (lane == 31) ws[wid] = x;
    __syncthreads();
    if (wid == 0) {
        int s = (lane < 8) ? ws[lane] : 0;
        #pragma unroll
        for (int o = 1; o < 8; o <<= 1) {
            int y = __shfl_up_sync(0xFFFFFFFFu, s, o);
            if (lane >= o) s += y;
        }
        ws[lane] = s;
    }
    __syncthreads();
    int incl = x + (wid > 0 ? ws[wid - 1] : 0);
    if (tid < nblocks) g_part[tid] = incl - v;
    if (tid == nblocks - 1) g_ptr[n] = incl;
}

// scan stage C: intra-block exclusive scan + block offset -> g_ptr
__global__ void scanC_kernel(int n) {
    int i = blockIdx.x * blockDim.x + threadIdx.x;
    int lane = threadIdx.x & 31, wid = threadIdx.x >> 5;
    __shared__ int ws[SCAN_TPB / 32];
    int v = (i < n) ? (g_deg[i] - 1) : 0;
    int x = v;
    #pragma unroll
    for (int o = 1; o < 32; o <<= 1) {
        int y = __shfl_up_sync(0xFFFFFFFFu, x, o);
        if (lane >= o) x += y;
    }
    if (lane == 31) ws[wid] = x;
    __syncthreads();
    if (wid == 0) {
        int s = (lane < SCAN_TPB / 32) ? ws[lane] : 0;
        #pragma unroll
        for (int o = 1; o < SCAN_TPB / 32; o <<= 1) {
            int y = __shfl_up_sync(0xFFFFFFFFu, s, o);
            if (lane >= o) s += y;
        }
        ws[lane] = s;
    }
    __syncthreads();
    int incl = x + (wid > 0 ? ws[wid - 1] : 0);
    if (i < n) g_ptr[i] = incl - v + g_part[blockIdx.x];
}

__global__ void scatter_kernel(const int* __restrict__ ei, int E, int n) {
    int e = blockIdx.x * blockDim.x + threadIdx.x;
    if (e < E) {
        int r = clampN(ei[e], n);
        int c = clampN(ei[E + e], n);
        int pos = g_ptr[c] + atomicAdd(&g_cursor[c], 1);
        float w = g_dinv[r] * g_dinv[c];
        g_csr[pos] = make_int2(r, __float_as_int(w));
    }
}

// ---------------- fused MLP encode: warp/node, h1 stays in registers ------------
__global__ void mlp_kernel(const float* __restrict__ x,
                           const float* __restrict__ W1,
                           const float* __restrict__ b1,
                           const float* __restrict__ W2,
                           const float* __restrict__ b2, int n) {
    int warp = (blockIdx.x * blockDim.x + threadIdx.x) >> 5;
    int lane = threadIdx.x & 31;
    if (warp >= n) return;
    const float* xr = x + (size_t)warp * FIN;
    unsigned long long acc;
    PACK2(acc, b1[2 * lane], b1[2 * lane + 1]);
    for (int kb = 0; kb < FIN; kb += 32) {
        float xv = xr[kb + lane];
        #pragma unroll
        for (int j = 0; j < 32; j++) {
            float xk = __shfl_sync(0xFFFFFFFFu, xv, j);
            unsigned long long xk2, wv;
            PACK2(xk2, xk, xk);
            wv = *(const unsigned long long*)&W1[(kb + j) * FH + 2 * lane];
            FMA2(acc, xk2, wv, acc);
        }
    }
    float a0, a1;
    UNPACK2(a0, a1, acc);
    a0 = fmaxf(a0, 0.0f);                    // h1 feats (2l, 2l+1) in registers
    a1 = fmaxf(a1, 0.0f);

    unsigned long long acc2;
    PACK2(acc2, b2[2 * lane], b2[2 * lane + 1]);
    #pragma unroll
    for (int j = 0; j < 32; j++) {
        float h0j = __shfl_sync(0xFFFFFFFFu, a0, j);   // h1 feat 2j
        float h1j = __shfl_sync(0xFFFFFFFFu, a1, j);   // h1 feat 2j+1
        unsigned long long hp0, hp1, wv0, wv1;
        PACK2(hp0, h0j, h0j);
        PACK2(hp1, h1j, h1j);
        wv0 = *(const unsigned long long*)&W2[(2 * j) * FH + 2 * lane];
        wv1 = *(const unsigned long long*)&W2[(2 * j + 1) * FH + 2 * lane];
        FMA2(acc2, hp0, wv0, acc2);
        FMA2(acc2, hp1, wv1, acc2);
    }
    float c0, c1;
    UNPACK2(c0, c1, acc2);
    g_hA[warp * 32 + lane] = __floats2half2_rn(c0, c1);   // features (2l, 2l+1)
    g_h0[warp * 32 + lane] = make_float2(c0, c1);
}

// ---------------- persistent APPNP: all K steps in one launch -------------------
__device__ __forceinline__ void grid_sync_dev(unsigned nblocks) {
    __syncthreads();
    if (threadIdx.x == 0) {
        __threadfence();
        unsigned gen = *(volatile unsigned*)&g_bar_gen;
        unsigned t = atomicAdd(&g_bar_count, 1u);
        if (t == nblocks - 1u) {
            atomicExch(&g_bar_count, 0u);
            __threadfence();
            *(volatile unsigned*)&g_bar_gen = gen + 1u;
        } else {
            while (*(volatile unsigned*)&g_bar_gen == gen) __nanosleep(32);
        }
        __threadfence();
    }
    __syncthreads();
}

__global__ void __launch_bounds__(256, 4)
prop_persistent(const float* __restrict__ Wf,
                const float* __restrict__ bf,
                float* __restrict__ out, int n) {
    int lane = threadIdx.x & 31;
    int warpG = (blockIdx.x * blockDim.x + threadIdx.x) >> 5;
    int nwarps = (gridDim.x * blockDim.x) >> 5;
    int nnodes = n;

    for (int t = 0; t < KSTEPS; t++) {
        const __half2* __restrict__ hin  = (t & 1) ? g_hB : g_hA;
        __half2*       __restrict__ hout = (t & 1) ? g_hA : g_hB;
        int decode = (t == KSTEPS - 1);

        for (int node = warpG; node < nnodes; node += nwarps) {
            int e    = g_ptr[node];        // scalar loads: node may be odd,
            int eend = g_ptr[node + 1];    // so no int2 (8B-aligned) view here

            float di = g_dinv[node];
            float wself = di * di;
            float2 hv = __half22float2(__ldcg(&hin[node * 32 + lane]));
            float ax = wself * hv.x;
            float ay = wself * hv.y;

            for (; e + 4 <= eend; e += 4) {
                int2 s0 = g_csr[e + 0];
                int2 s1 = g_csr[e + 1];
                int2 s2 = g_csr[e + 2];
                int2 s3 = g_csr[e + 3];
                __half2 v0 = __ldcg(&hin[s0.x * 32 + lane]);
                __half2 v1 = __ldcg(&hin[s1.x * 32 + lane]);
                __half2 v2 = __ldcg(&hin[s2.x * 32 + lane]);
                __half2 v3 = __ldcg(&hin[s3.x * 32 + lane]);
                float2 f0 = __half22float2(v0);
                float2 f1 = __half22float2(v1);
                float2 f2 = __half22float2(v2);
                float2 f3 = __half22float2(v3);
                float w0 = __int_as_float(s0.y);
                float w1 = __int_as_float(s1.y);
                float w2 = __int_as_float(s2.y);
                float w3 = __int_as_float(s3.y);
                ax = fmaf(w0, f0.x, ax); ay = fmaf(w0, f0.y, ay);
                ax = fmaf(w1, f1.x, ax); ay = fmaf(w1, f1.y, ay);
                ax = fmaf(w2, f2.x, ax); ay = fmaf(w2, f2.y, ay);
                ax = fmaf(w3, f3.x, ax); ay = fmaf(w3, f3.y, ay);
            }
            for (; e < eend; e++) {
                int2 s = g_csr[e];
                float2 f = __half22float2(__ldcg(&hin[s.x * 32 + lane]));
                float w = __int_as_float(s.y);
                ax = fmaf(w, f.x, ax);
                ay = fmaf(w, f.y, ay);
            }

            float2 t0 = g_h0[node * 32 + lane];
            float ox = 0.9f * ax + 0.1f * t0.x;
            float oy = 0.9f * ay + 0.1f * t0.y;

            if (!decode) {
                hout[node * 32 + lane] = __floats2half2_rn(ox, oy);
            } else {
                float acc0 = bf[lane];
                float acc1 = (lane < FOUT - 32) ? bf[lane + 32] : 0.0f;
                #pragma unroll
                for (int j = 0; j < 32; j++) {
                    float hx = __shfl_sync(0xFFFFFFFFu, ox, j);   // feature 2j
                    float hy = __shfl_sync(0xFFFFFFFFu, oy, j);   // feature 2j+1
                    acc0 = fmaf(hx, Wf[(2 * j) * FOUT + lane], acc0);
                    acc0 = fmaf(hy, Wf[(2 * j + 1) * FOUT + lane], acc0);
                    if (lane < FOUT - 32) {
                        acc1 = fmaf(hx, Wf[(2 * j) * FOUT + lane + 32], acc1);
                        acc1 = fmaf(hy, Wf[(2 * j + 1) * FOUT + lane + 32], acc1);
                    }
                }
                out[(size_t)node * FOUT + lane] = acc0;
                if (lane < FOUT - 32)
                    out[(size_t)node * FOUT + lane + 32] = acc1;
            }
        }
        if (t != KSTEPS - 1) grid_sync_dev(gridDim.x);
    }
}

// ---------------- launch ----------------
extern "C" void kernel_launch(void* const* d_in, const int* in_sizes, int n_in,
                              void* d_out, int out_size) {
    const float* x  = (const float*)d_in[0];
    const int*   ei = (const int*)d_in[1];
    const float* W1 = (const float*)d_in[2];
    const float* b1 = (const float*)d_in[3];
    const float* W2 = (const float*)d_in[4];
    const float* b2 = (const float*)d_in[5];
    const float* Wf = (const float*)d_in[6];
    const float* bf = (const float*)d_in[7];
    float* out = (float*)d_out;

    int N = in_sizes[0] / FIN;
    int E = in_sizes[1] / 2;
    if (N > MAXN) N = MAXN;
    if (E > MAXE) E = MAXE;

    int sms = 148;
    cudaDeviceGetAttribute(&sms, cudaDevAttrMultiProcessorCount, 0);

    int tpb = 256;
    int nblk = (N + SCAN_TPB - 1) / SCAN_TPB;

    init_kernel<<<(N + tpb - 1) / tpb, tpb>>>(N);
    hist_kernel<<<(E + tpb - 1) / tpb, tpb>>>(ei, E, N);
    scanA_kernel<<<nblk, SCAN_TPB>>>(N);          // also computes dinv
    scanB_kernel<<<1, MAXBLK>>>(nblk, N);
    scanC_kernel<<<nblk, SCAN_TPB>>>(N);
    scatter_kernel<<<(E + tpb - 1) / tpb, tpb>>>(ei, E, N);

    int wblocks = (N + 7) / 8;
    mlp_kernel<<<wblocks, tpb>>>(x, W1, b1, W2, b2, N);

    // one persistent launch for all K steps; __launch_bounds__(256,4)
    // guarantees 4 co-resident blocks/SM (64 regs cap, 0 smem)
    int pgrid = sms * 4;
    prop_persistent<<<pgrid, tpb>>>(Wf, bf, out, N);
}

// round 10
// speedup vs baseline: 1.0007x; 1.0007x over previous
#include <cuda_runtime.h>
#include <cuda_fp16.h>
#include <cstdint>

#define MAXN 50000
#define MAXE 800000
#define FIN 256
#define FH  64
#define FOUT 40
#define KSTEPS 10
#define SCAN_TPB 256
#define MAXBLK 256

// packed fp32x2 helpers (Blackwell dual fp32)
#define PACK2(out, lo, hi) asm("mov.b64 %0, {%1, %2};" : "=l"(out) : "f"(lo), "f"(hi))
#define UNPACK2(lo, hi, in) asm("mov.b64 {%0, %1}, %2;" : "=f"(lo), "=f"(hi) : "l"(in))
#define FMA2(d, a, b, c) asm("fma.rn.f32x2 %0, %1, %2, %3;" : "=l"(d) : "l"(a), "l"(b), "l"(c))

// ---------------- static device scratch ----------------
__device__ int      g_deg[MAXN];
__device__ float    g_dinv[MAXN];
__device__ int      g_ptr[MAXN + 1];
__device__ int      g_cursor[MAXN];
__device__ int      g_part[MAXBLK];
__device__ unsigned g_bar_count;     // persistent-kernel barrier
__device__ unsigned g_bar_gen;
__device__ __align__(16) int2    g_csr[MAXE];
// feature pairing: slot p of a node = features (2p, 2p+1)
__device__ __align__(16) float2  g_h0[MAXN * 32];
__device__ __align__(16) __half2 g_hA[MAXN * 32];
__device__ __align__(16) __half2 g_hB[MAXN * 32];

__device__ __forceinline__ int clampN(int v, int n) {
    v = v < 0 ? 0 : v;
    return v >= n ? n - 1 : v;
}

// ---------------- graph preprocessing ----------------
__global__ void init_kernel(int n) {
    int i = blockIdx.x * blockDim.x + threadIdx.x;
    if (i < n) { g_deg[i] = 1; g_cursor[i] = 0; }   // self loop
}

__global__ void hist_kernel(const int* __restrict__ ei, int E, int n) {
    int e = blockIdx.x * blockDim.x + threadIdx.x;
    if (e < E) atomicAdd(&g_deg[clampN(ei[E + e], n)], 1);
}

// scan stage A: per-block sums of (deg-1); also computes dinv
__global__ void scanA_kernel(int n) {
    int i = blockIdx.x * blockDim.x + threadIdx.x;
    int lane = threadIdx.x & 31, wid = threadIdx.x >> 5;
    __shared__ int ws[SCAN_TPB / 32];
    int d = (i < n) ? g_deg[i] : 1;
    if (i < n) g_dinv[i] = rsqrtf((float)d);
    int v = (i < n) ? (d - 1) : 0;
    #pragma unroll
    for (int o = 16; o > 0; o >>= 1) v += __shfl_down_sync(0xFFFFFFFFu, v, o);
    if (lane == 0) ws[wid] = v;
    __syncthreads();
    if (wid == 0) {
        int s = (lane < SCAN_TPB / 32) ? ws[lane] : 0;
        #pragma unroll
        for (int o = 16; o > 0; o >>= 1) s += __shfl_down_sync(0xFFFFFFFFu, s, o);
        if (lane == 0) g_part[blockIdx.x] = s;
    }
}

// scan stage B: exclusive scan of block partials (single block)
__global__ void scanB_kernel(int nblocks, int n) {
    int tid = threadIdx.x, lane = tid & 31, wid = tid >> 5;
    __shared__ int ws[8];
    int v = (tid < nblocks) ? g_part[tid] : 0;
    int x = v;
    #pragma unroll
    for (int o = 1; o < 32; o <<= 1) {
        int y = __shfl_up_sync(0xFFFFFFFFu, x, o);
        if (lane >= o) x += y;
    }
    if (lane == 31) ws[wid] = x;
    __syncthreads();
    if (wid == 0) {
        int s = (lane < 8) ? ws[lane] : 0;
        #pragma unroll
        for (int o = 1; o < 8; o <<= 1) {
            int y = __shfl_up_sync(0xFFFFFFFFu, s, o);
            if (lane >= o) s += y;
        }
        ws[lane] = s;
    }
    __syncthreads();
    int incl = x + (wid > 0 ? ws[wid - 1] : 0);
    if (tid < nblocks) g_part[tid] = incl - v;
    if (tid == nblocks - 1) g_ptr[n] = incl;
}

// scan stage C: intra-block exclusive scan + block offset -> g_ptr
__global__ void scanC_kernel(int n) {
    int i = blockIdx.x * blockDim.x + threadIdx.x;
    int lane = threadIdx.x & 31, wid = threadIdx.x >> 5;
    __shared__ int ws[SCAN_TPB / 32];
    int v = (i < n) ? (g_deg[i] - 1) : 0;
    int x = v;
    #pragma unroll
    for (int o = 1; o < 32; o <<= 1) {
        int y = __shfl_up_sync(0xFFFFFFFFu, x, o);
        if (lane >= o) x += y;
    }
    if (lane == 31) ws[wid] = x;
    __syncthreads();
    if (wid == 0) {
        int s = (lane < SCAN_TPB / 32) ? ws[lane] : 0;
        #pragma unroll
        for (int o = 1; o < SCAN_TPB / 32; o <<= 1) {
            int y = __shfl_up_sync(0xFFFFFFFFu, s, o);
            if (lane >= o) s += y;
        }
        ws[lane] = s;
    }
    __syncthreads();
    int incl = x + (wid > 0 ? ws[wid - 1] : 0);
    if (i < n) g_ptr[i] = incl - v + g_part[blockIdx.x];
}

__global__ void scatter_kernel(const int* __restrict__ ei, int E, int n) {
    int e = blockIdx.x * blockDim.x + threadIdx.x;
    if (e < E) {
        int r = clampN(ei[e], n);
        int c = clampN(ei[E + e], n);
        int pos = g_ptr[c] + atomicAdd(&g_cursor[c], 1);
        float w = g_dinv[r] * g_dinv[c];
        g_csr[pos] = make_int2(r, __float_as_int(w));
    }
}

// ---------------- fused MLP encode: warp/node, h1 stays in registers ------------
__global__ void mlp_kernel(const float* __restrict__ x,
                           const float* __restrict__ W1,
                           const float* __restrict__ b1,
                           const float* __restrict__ W2,
                           const float* __restrict__ b2, int n) {
    int warp = (blockIdx.x * blockDim.x + threadIdx.x) >> 5;
    int lane = threadIdx.x & 31;
    if (warp >= n) return;
    const float* xr = x + (size_t)warp * FIN;
    unsigned long long acc;
    PACK2(acc, b1[2 * lane], b1[2 * lane + 1]);
    for (int kb = 0; kb < FIN; kb += 32) {
        float xv = xr[kb + lane];
        #pragma unroll
        for (int j = 0; j < 32; j++) {
            float xk = __shfl_sync(0xFFFFFFFFu, xv, j);
            unsigned long long xk2, wv;
            PACK2(xk2, xk, xk);
            wv = *(const unsigned long long*)&W1[(kb + j) * FH + 2 * lane];
            FMA2(acc, xk2, wv, acc);
        }
    }
    float a0, a1;
    UNPACK2(a0, a1, acc);
    a0 = fmaxf(a0, 0.0f);                    // h1 feats (2l, 2l+1) in registers
    a1 = fmaxf(a1, 0.0f);

    unsigned long long acc2;
    PACK2(acc2, b2[2 * lane], b2[2 * lane + 1]);
    #pragma unroll
    for (int j = 0; j < 32; j++) {
        float h0j = __shfl_sync(0xFFFFFFFFu, a0, j);   // h1 feat 2j
        float h1j = __shfl_sync(0xFFFFFFFFu, a1, j);   // h1 feat 2j+1
        unsigned long long hp0, hp1, wv0, wv1;
        PACK2(hp0, h0j, h0j);
        PACK2(hp1, h1j, h1j);
        wv0 = *(const unsigned long long*)&W2[(2 * j) * FH + 2 * lane];
        wv1 = *(const unsigned long long*)&W2[(2 * j + 1) * FH + 2 * lane];
        FMA2(acc2, hp0, wv0, acc2);
        FMA2(acc2, hp1, wv1, acc2);
    }
    float c0, c1;
    UNPACK2(c0, c1, acc2);
    g_hA[warp * 32 + lane] = __floats2half2_rn(c0, c1);   // features (2l, 2l+1)
    g_h0[warp * 32 + lane] = make_float2(c0, c1);
}

// ---------------- persistent APPNP: all K steps in one launch -------------------
// After the barrier, EVERY thread executes __threadfence() (fence.gpu). On
// Blackwell, fence scope >= cluster makes ptxas emit CCTL.IVALL, which
// invalidates this SM's L1D — replicating the per-launch L1 flush that made
// the multi-launch version coherent, while letting plain loads use L1 within
// a step (the R9 __ldcg version lost all L1 reuse and regressed).
__device__ __forceinline__ void grid_sync_dev(unsigned nblocks) {
    __syncthreads();
    if (threadIdx.x == 0) {
        __threadfence();
        unsigned gen = *(volatile unsigned*)&g_bar_gen;
        unsigned t = atomicAdd(&g_bar_count, 1u);
        if (t == nblocks - 1u) {
            atomicExch(&g_bar_count, 0u);
            __threadfence();
            *(volatile unsigned*)&g_bar_gen = gen + 1u;
        } else {
            while (*(volatile unsigned*)&g_bar_gen == gen) __nanosleep(32);
        }
    }
    __syncthreads();
    __threadfence();   // all threads: L1D invalidate + acquire ordering
}

__global__ void __launch_bounds__(256, 4)
prop_persistent(const float* __restrict__ Wf,
                const float* __restrict__ bf,
                float* __restrict__ out, int n) {
    int lane = threadIdx.x & 31;
    int warpG = (blockIdx.x * blockDim.x + threadIdx.x) >> 5;
    int nwarps = (gridDim.x * blockDim.x) >> 5;

    for (int t = 0; t < KSTEPS; t++) {
        const __half2* __restrict__ hin  = (t & 1) ? g_hB : g_hA;
        __half2*       __restrict__ hout = (t & 1) ? g_hA : g_hB;
        int decode = (t == KSTEPS - 1);

        for (int node = warpG; node < n; node += nwarps) {
            int e    = g_ptr[node];        // scalar loads (node may be odd)
            int eend = g_ptr[node + 1];

            float di = g_dinv[node];
            float wself = di * di;
            float2 hv = __half22float2(hin[node * 32 + lane]);
            float ax = wself * hv.x;
            float ay = wself * hv.y;

            for (; e + 4 <= eend; e += 4) {
                int2 s0 = g_csr[e + 0];
                int2 s1 = g_csr[e + 1];
                int2 s2 = g_csr[e + 2];
                int2 s3 = g_csr[e + 3];
                __half2 v0 = hin[s0.x * 32 + lane];   // plain loads: L1-cached
                __half2 v1 = hin[s1.x * 32 + lane];
                __half2 v2 = hin[s2.x * 32 + lane];
                __half2 v3 = hin[s3.x * 32 + lane];
                float2 f0 = __half22float2(v0);
                float2 f1 = __half22float2(v1);
                float2 f2 = __half22float2(v2);
                float2 f3 = __half22float2(v3);
                float w0 = __int_as_float(s0.y);
                float w1 = __int_as_float(s1.y);
                float w2 = __int_as_float(s2.y);
                float w3 = __int_as_float(s3.y);
                ax = fmaf(w0, f0.x, ax); ay = fmaf(w0, f0.y, ay);
                ax = fmaf(w1, f1.x, ax); ay = fmaf(w1, f1.y, ay);
                ax = fmaf(w2, f2.x, ax); ay = fmaf(w2, f2.y, ay);
                ax = fmaf(w3, f3.x, ax); ay = fmaf(w3, f3.y, ay);
            }
            for (; e < eend; e++) {
                int2 s = g_csr[e];
                float2 f = __half22float2(hin[s.x * 32 + lane]);
                float w = __int_as_float(s.y);
                ax = fmaf(w, f.x, ax);
                ay = fmaf(w, f.y, ay);
            }

            float2 t0 = g_h0[node * 32 + lane];
            float ox = 0.9f * ax + 0.1f * t0.x;
            float oy = 0.9f * ay + 0.1f * t0.y;

            if (!decode) {
                hout[node * 32 + lane] = __floats2half2_rn(ox, oy);
            } else {
                float acc0 = bf[lane];
                float acc1 = (lane < FOUT - 32) ? bf[lane + 32] : 0.0f;
                #pragma unroll
                for (int j = 0; j < 32; j++) {
                    float hx = __shfl_sync(0xFFFFFFFFu, ox, j);   // feature 2j
                    float hy = __shfl_sync(0xFFFFFFFFu, oy, j);   // feature 2j+1
                    acc0 = fmaf(hx, Wf[(2 * j) * FOUT + lane], acc0);
                    acc0 = fmaf(hy, Wf[(2 * j + 1) * FOUT + lane], acc0);
                    if (lane < FOUT - 32) {
                        acc1 = fmaf(hx, Wf[(2 * j) * FOUT + lane + 32], acc1);
                        acc1 = fmaf(hy, Wf[(2 * j + 1) * FOUT + lane + 32], acc1);
                    }
                }
                out[(size_t)node * FOUT + lane] = acc0;
                if (lane < FOUT - 32)
                    out[(size_t)node * FOUT + lane + 32] = acc1;
            }
        }
        if (t != KSTEPS - 1) grid_sync_dev(gridDim.x);
    }
}

// ---------------- launch ----------------
extern "C" void kernel_launch(void* const* d_in, const int* in_sizes, int n_in,
                              void* d_out, int out_size) {
    const float* x  = (const float*)d_in[0];
    const int*   ei = (const int*)d_in[1];
    const float* W1 = (const float*)d_in[2];
    const float* b1 = (const float*)d_in[3];
    const float* W2 = (const float*)d_in[4];
    const float* b2 = (const float*)d_in[5];
    const float* Wf = (const float*)d_in[6];
    const float* bf = (const float*)d_in[7];
    float* out = (float*)d_out;

    int N = in_sizes[0] / FIN;
    int E = in_sizes[1] / 2;
    if (N > MAXN) N = MAXN;
    if (E > MAXE) E = MAXE;

    int sms = 148;
    cudaDeviceGetAttribute(&sms, cudaDevAttrMultiProcessorCount, 0);

    int tpb = 256;
    int nblk = (N + SCAN_TPB - 1) / SCAN_TPB;

    init_kernel<<<(N + tpb - 1) / tpb, tpb>>>(N);
    hist_kernel<<<(E + tpb - 1) / tpb, tpb>>>(ei, E, N);
    scanA_kernel<<<nblk, SCAN_TPB>>>(N);          // also computes dinv
    scanB_kernel<<<1, MAXBLK>>>(nblk, N);
    scanC_kernel<<<nblk, SCAN_TPB>>>(N);
    scatter_kernel<<<(E + tpb - 1) / tpb, tpb>>>(ei, E, N);

    int wblocks = (N + 7) / 8;
    mlp_kernel<<<wblocks, tpb>>>(x, W1, b1, W2, b2, N);

    // one persistent launch for all K steps; __launch_bounds__(256,4)
    // guarantees 4 co-resident blocks/SM (64 regs cap, 0 smem)
    int pgrid = sms * 4;
    prop_persistent<<<pgrid, tpb>>>(Wf, bf, out, N);
}

// round 11
// speedup vs baseline: 1.1337x; 1.1329x over previous
#include <cuda_runtime.h>
#include <cuda_fp16.h>
#include <cstdint>

#define MAXN 50000
#define MAXE 800000
#define FIN 256
#define FH  64
#define FOUT 40
#define KSTEPS 10
#define SCAN_TPB 256
#define MAXBLK 256

// packed fp32x2 helpers (Blackwell dual fp32)
#define PACK2(out, lo, hi) asm("mov.b64 %0, {%1, %2};" : "=l"(out) : "f"(lo), "f"(hi))
#define UNPACK2(lo, hi, in) asm("mov.b64 {%0, %1}, %2;" : "=f"(lo), "=f"(hi) : "l"(in))
#define FMA2(d, a, b, c) asm("fma.rn.f32x2 %0, %1, %2, %3;" : "=l"(d) : "l"(a), "l"(b), "l"(c))

// ---------------- static device scratch ----------------
__device__ int     g_deg[MAXN];
__device__ float   g_dinv[MAXN];
__device__ int     g_ptr[MAXN + 1];
__device__ int     g_cursor[MAXN];
__device__ int     g_part[MAXBLK];
__device__ __align__(16) int2    g_csr[MAXE];
// feature pairing: slot p of a node = features (2p, 2p+1)
__device__ __align__(16) float2  g_h0[MAXN * 32];
__device__ __align__(16) __half2 g_hA[MAXN * 32];
__device__ __align__(16) __half2 g_hB[MAXN * 32];

__device__ __forceinline__ int clampN(int v, int n) {
    v = v < 0 ? 0 : v;
    return v >= n ? n - 1 : v;
}

// ---------------- graph preprocessing ----------------
__global__ void init_kernel(int n) {
    int i = blockIdx.x * blockDim.x + threadIdx.x;
    if (i < n) { g_deg[i] = 1; g_cursor[i] = 0; }   // self loop
}

__global__ void hist_kernel(const int* __restrict__ ei, int E, int n) {
    int e = blockIdx.x * blockDim.x + threadIdx.x;
    if (e < E) atomicAdd(&g_deg[clampN(ei[E + e], n)], 1);
}

// scan stage A: per-block sums of (deg-1); also computes dinv
__global__ void scanA_kernel(int n) {
    int i = blockIdx.x * blockDim.x + threadIdx.x;
    int lane = threadIdx.x & 31, wid = threadIdx.x >> 5;
    __shared__ int ws[SCAN_TPB / 32];
    int d = (i < n) ? g_deg[i] : 1;
    if (i < n) g_dinv[i] = rsqrtf((float)d);
    int v = (i < n) ? (d - 1) : 0;
    #pragma unroll
    for (int o = 16; o > 0; o >>= 1) v += __shfl_down_sync(0xFFFFFFFFu, v, o);
    if (lane == 0) ws[wid] = v;
    __syncthreads();
    if (wid == 0) {
        int s = (lane < SCAN_TPB / 32) ? ws[lane] : 0;
        #pragma unroll
        for (int o = 16; o > 0; o >>= 1) s += __shfl_down_sync(0xFFFFFFFFu, s, o);
        if (lane == 0) g_part[blockIdx.x] = s;
    }
}

// scan stage B: exclusive scan of block partials (single block)
__global__ void scanB_kernel(int nblocks, int n) {
    int tid = threadIdx.x, lane = tid & 31, wid = tid >> 5;
    __shared__ int ws[8];
    int v = (tid < nblocks) ? g_part[tid] : 0;
    int x = v;
    #pragma unroll
    for (int o = 1; o < 32; o <<= 1) {
        int y = __shfl_up_sync(0xFFFFFFFFu, x, o);
        if (lane >= o) x += y;
    }
    if (lane == 31) ws[wid] = x;
    __syncthreads();
    if (wid == 0) {
        int s = (lane < 8) ? ws[lane] : 0;
        #pragma unroll
        for (int o = 1; o < 8; o <<= 1) {
            int y = __shfl_up_sync(0xFFFFFFFFu, s, o);
            if (lane >= o) s += y;
        }
        ws[lane] = s;
    }
    __syncthreads();
    int incl = x + (wid > 0 ? ws[wid - 1] : 0);
    if (tid < nblocks) g_part[tid] = incl - v;
    if (tid == nblocks - 1) g_ptr[n] = incl;
}

// scan stage C: intra-block exclusive scan + block offset -> g_ptr
__global__ void scanC_kernel(int n) {
    int i = blockIdx.x * blockDim.x + threadIdx.x;
    int lane = threadIdx.x & 31, wid = threadIdx.x >> 5;
    __shared__ int ws[SCAN_TPB / 32];
    int v = (i < n) ? (g_deg[i] - 1) : 0;
    int x = v;
    #pragma unroll
    for (int o = 1; o < 32; o <<= 1) {
        int y = __shfl_up_sync(0xFFFFFFFFu, x, o);
        if (lane >= o) x += y;
    }
    if (lane == 31) ws[wid] = x;
    __syncthreads();
    if (wid == 0) {
        int s = (lane < SCAN_TPB / 32) ? ws[lane] : 0;
        #pragma unroll
        for (int o = 1; o < SCAN_TPB / 32; o <<= 1) {
            int y = __shfl_up_sync(0xFFFFFFFFu, s, o);
            if (lane >= o) s += y;
        }
        ws[lane] = s;
    }
    __syncthreads();
    int incl = x + (wid > 0 ? ws[wid - 1] : 0);
    if (i < n) g_ptr[i] = incl - v + g_part[blockIdx.x];
}

__global__ void scatter_kernel(const int* __restrict__ ei, int E, int n) {
    int e = blockIdx.x * blockDim.x + threadIdx.x;
    if (e < E) {
        int r = clampN(ei[e], n);
        int c = clampN(ei[E + e], n);
        int pos = g_ptr[c] + atomicAdd(&g_cursor[c], 1);
        float w = g_dinv[r] * g_dinv[c];
        g_csr[pos] = make_int2(r, __float_as_int(w));
    }
}

// ---------------- fused MLP encode: warp/node, h1 stays in registers ------------
__global__ void mlp_kernel(const float* __restrict__ x,
                           const float* __restrict__ W1,
                           const float* __restrict__ b1,
                           const float* __restrict__ W2,
                           const float* __restrict__ b2, int n) {
    int warp = (blockIdx.x * blockDim.x + threadIdx.x) >> 5;
    int lane = threadIdx.x & 31;
    if (warp >= n) return;
    const float* xr = x + (size_t)warp * FIN;
    unsigned long long acc;
    PACK2(acc, b1[2 * lane], b1[2 * lane + 1]);
    for (int kb = 0; kb < FIN; kb += 32) {
        float xv = xr[kb + lane];
        #pragma unroll
        for (int j = 0; j < 32; j++) {
            float xk = __shfl_sync(0xFFFFFFFFu, xv, j);
            unsigned long long xk2, wv;
            PACK2(xk2, xk, xk);
            wv = *(const unsigned long long*)&W1[(kb + j) * FH + 2 * lane];
            FMA2(acc, xk2, wv, acc);
        }
    }
    float a0, a1;
    UNPACK2(a0, a1, acc);
    a0 = fmaxf(a0, 0.0f);                    // h1 feats (2l, 2l+1) in registers
    a1 = fmaxf(a1, 0.0f);

    unsigned long long acc2;
    PACK2(acc2, b2[2 * lane], b2[2 * lane + 1]);
    #pragma unroll
    for (int j = 0; j < 32; j++) {
        float h0j = __shfl_sync(0xFFFFFFFFu, a0, j);   // h1 feat 2j
        float h1j = __shfl_sync(0xFFFFFFFFu, a1, j);   // h1 feat 2j+1
        unsigned long long hp0, hp1, wv0, wv1;
        PACK2(hp0, h0j, h0j);
        PACK2(hp1, h1j, h1j);
        wv0 = *(const unsigned long long*)&W2[(2 * j) * FH + 2 * lane];
        wv1 = *(const unsigned long long*)&W2[(2 * j + 1) * FH + 2 * lane];
        FMA2(acc2, hp0, wv0, acc2);
        FMA2(acc2, hp1, wv1, acc2);
    }
    float c0, c1;
    UNPACK2(c0, c1, acc2);
    g_hA[warp * 32 + lane] = __floats2half2_rn(c0, c1);   // features (2l, 2l+1)
    g_h0[warp * 32 + lane] = make_float2(c0, c1);
}

// ---------------- APPNP step: warp/node, uniform CSR loads, unroll x4 ----------
template <int SRC_A, int DECODE>
__global__ void prop_kernel(const float* __restrict__ Wf,
                            const float* __restrict__ bf,
                            float* __restrict__ out, int n) {
    int node = (blockIdx.x * blockDim.x + threadIdx.x) >> 5;
    int lane = threadIdx.x & 31;
    if (node >= n) return;
    const __half2* __restrict__ hin  = SRC_A ? g_hA : g_hB;
    __half2*       __restrict__ hout = SRC_A ? g_hB : g_hA;

    int start = g_ptr[node];
    int end   = g_ptr[node + 1];

    float di = g_dinv[node];
    float wself = di * di;
    float2 hv = __half22float2(hin[node * 32 + lane]);
    float ax = wself * hv.x;
    float ay = wself * hv.y;

    int e = start;
    for (; e + 4 <= end; e += 4) {
        int2 s0 = g_csr[e + 0];          // uniform (broadcast) loads
        int2 s1 = g_csr[e + 1];
        int2 s2 = g_csr[e + 2];
        int2 s3 = g_csr[e + 3];
        __half2 v0 = hin[s0.x * 32 + lane];  // 4 independent gathers in flight
        __half2 v1 = hin[s1.x * 32 + lane];
        __half2 v2 = hin[s2.x * 32 + lane];
        __half2 v3 = hin[s3.x * 32 + lane];
        float2 f0 = __half22float2(v0);
        float2 f1 = __half22float2(v1);
        float2 f2 = __half22float2(v2);
        float2 f3 = __half22float2(v3);
        float w0 = __int_as_float(s0.y);
        float w1 = __int_as_float(s1.y);
        float w2 = __int_as_float(s2.y);
        float w3 = __int_as_float(s3.y);
        ax = fmaf(w0, f0.x, ax);  ay = fmaf(w0, f0.y, ay);
        ax = fmaf(w1, f1.x, ax);  ay = fmaf(w1, f1.y, ay);
        ax = fmaf(w2, f2.x, ax);  ay = fmaf(w2, f2.y, ay);
        ax = fmaf(w3, f3.x, ax);  ay = fmaf(w3, f3.y, ay);
    }
    for (; e < end; e++) {
        int2 s = g_csr[e];
        float2 f = __half22float2(hin[s.x * 32 + lane]);
        float w = __int_as_float(s.y);
        ax = fmaf(w, f.x, ax);
        ay = fmaf(w, f.y, ay);
    }

    float2 t = g_h0[node * 32 + lane];
    float ox = 0.9f * ax + 0.1f * t.x;     // features (2l, 2l+1), fp32
    float oy = 0.9f * ay + 0.1f * t.y;

    if (!DECODE) {
        hout[node * 32 + lane] = __floats2half2_rn(ox, oy);
    } else {
        // fused decode: out[node] = h @ Wf + bf (h in registers, fp32)
        float acc0 = bf[lane];
        float acc1 = (lane < FOUT - 32) ? bf[lane + 32] : 0.0f;
        #pragma unroll
        for (int j = 0; j < 32; j++) {
            float hx = __shfl_sync(0xFFFFFFFFu, ox, j);   // feature 2j
            float hy = __shfl_sync(0xFFFFFFFFu, oy, j);   // feature 2j+1
            acc0 = fmaf(hx, Wf[(2 * j) * FOUT + lane], acc0);
            acc0 = fmaf(hy, Wf[(2 * j + 1) * FOUT + lane], acc0);
            if (lane < FOUT - 32) {
                acc1 = fmaf(hx, Wf[(2 * j) * FOUT + lane + 32], acc1);
                acc1 = fmaf(hy, Wf[(2 * j + 1) * FOUT + lane + 32], acc1);
            }
        }
        out[(size_t)node * FOUT + lane] = acc0;
        if (lane < FOUT - 32)
            out[(size_t)node * FOUT + lane + 32] = acc1;
    }
}

// ---------------- launch ----------------
extern "C" void kernel_launch(void* const* d_in, const int* in_sizes, int n_in,
                              void* d_out, int out_size) {
    const float* x  = (const float*)d_in[0];
    const int*   ei = (const int*)d_in[1];
    const float* W1 = (const float*)d_in[2];
    const float* b1 = (const float*)d_in[3];
    const float* W2 = (const float*)d_in[4];
    const float* b2 = (const float*)d_in[5];
    const float* Wf = (const float*)d_in[6];
    const float* bf = (const float*)d_in[7];
    float* out = (float*)d_out;

    int N = in_sizes[0] / FIN;
    int E = in_sizes[1] / 2;
    if (N > MAXN) N = MAXN;
    if (E > MAXE) E = MAXE;

    int tpb = 256;
    int nblk = (N + SCAN_TPB - 1) / SCAN_TPB;

    init_kernel<<<(N + tpb - 1) / tpb, tpb>>>(N);
    hist_kernel<<<(E + tpb - 1) / tpb, tpb>>>(ei, E, N);
    scanA_kernel<<<nblk, SCAN_TPB>>>(N);          // also computes dinv
    scanB_kernel<<<1, MAXBLK>>>(nblk, N);
    scanC_kernel<<<nblk, SCAN_TPB>>>(N);
    scatter_kernel<<<(E + tpb - 1) / tpb, tpb>>>(ei, E, N);

    int wblocks = (N + 7) / 8;                 // 8 warps / 256-thread block
    mlp_kernel<<<wblocks, tpb>>>(x, W1, b1, W2, b2, N);   // fused mlp1+mlp2

    // steps 0..8 normal; step 9 (reads B) fuses the decode
    for (int t = 0; t < KSTEPS - 1; t++) {
        if ((t & 1) == 0) prop_kernel<1, 0><<<wblocks, tpb>>>(Wf, bf, out, N);
        else              prop_kernel<0, 0><<<wblocks, tpb>>>(Wf, bf, out, N);
    }
    prop_kernel<0, 1><<<wblocks, tpb>>>(Wf, bf, out, N);
}

// round 12
// speedup vs baseline: 1.1360x; 1.0020x over previous
#include <cuda_runtime.h>
#include <cuda_fp16.h>
#include <cstdint>

#define MAXN 50000
#define MAXE 800000
#define FIN 256
#define FH  64
#define FOUT 40
#define KSTEPS 10
#define SCAN_TPB 256
#define MAXBLK 256

// packed fp32x2 helpers (Blackwell dual fp32)
#define PACK2(out, lo, hi) asm("mov.b64 %0, {%1, %2};" : "=l"(out) : "f"(lo), "f"(hi))
#define UNPACK2(lo, hi, in) asm("mov.b64 {%0, %1}, %2;" : "=f"(lo), "=f"(hi) : "l"(in))
#define FMA2(d, a, b, c) asm("fma.rn.f32x2 %0, %1, %2, %3;" : "=l"(d) : "l"(a), "l"(b), "l"(c))

// ---------------- static device scratch ----------------
__device__ int     g_deg[MAXN];          // raw in-degree (no self loop), memset to 0
__device__ float   g_dinv[MAXN];
__device__ int     g_ptr[MAXN + 1];
__device__ int     g_cursor[MAXN];       // memset to 0
__device__ int     g_part[MAXBLK];
// csr entry: x = src node, y = weight as packed half2 (w,w)
__device__ __align__(16) int2    g_csr[MAXE];
// feature pairing: slot p of a node = features (2p, 2p+1); 128B rows, line-aligned
__device__ __align__(256) float2  g_h0[MAXN * 32];
__device__ __align__(256) __half2 g_hA[MAXN * 32];
__device__ __align__(256) __half2 g_hB[MAXN * 32];

__device__ __forceinline__ int clampN(int v, int n) {
    v = v < 0 ? 0 : v;
    return v >= n ? n - 1 : v;
}

// ---------------- graph preprocessing ----------------
__global__ void hist_kernel(const int* __restrict__ ei, int E, int n) {
    int e = blockIdx.x * blockDim.x + threadIdx.x;
    if (e < E) atomicAdd(&g_deg[clampN(ei[E + e], n)], 1);
}

// scan stage A: per-block sums of raw deg; also computes dinv (deg incl self = raw+1)
__global__ void scanA_kernel(int n) {
    int i = blockIdx.x * blockDim.x + threadIdx.x;
    int lane = threadIdx.x & 31, wid = threadIdx.x >> 5;
    __shared__ int ws[SCAN_TPB / 32];
    int draw = (i < n) ? g_deg[i] : 0;
    if (i < n) g_dinv[i] = rsqrtf((float)(draw + 1));
    int v = (i < n) ? draw : 0;
    #pragma unroll
    for (int o = 16; o > 0; o >>= 1) v += __shfl_down_sync(0xFFFFFFFFu, v, o);
    if (lane == 0) ws[wid] = v;
    __syncthreads();
    if (wid == 0) {
        int s = (lane < SCAN_TPB / 32) ? ws[lane] : 0;
        #pragma unroll
        for (int o = 16; o > 0; o >>= 1) s += __shfl_down_sync(0xFFFFFFFFu, s, o);
        if (lane == 0) g_part[blockIdx.x] = s;
    }
}

// scan stage B: exclusive scan of block partials (single block)
__global__ void scanB_kernel(int nblocks, int n) {
    int tid = threadIdx.x, lane = tid & 31, wid = tid >> 5;
    __shared__ int ws[8];
    int v = (tid < nblocks) ? g_part[tid] : 0;
    int x = v;
    #pragma unroll
    for (int o = 1; o < 32; o <<= 1) {
        int y = __shfl_up_sync(0xFFFFFFFFu, x, o);
        if (lane >= o) x += y;
    }
    if (lane == 31) ws[wid] = x;
    __syncthreads();
    if (wid == 0) {
        int s = (lane < 8) ? ws[lane] : 0;
        #pragma unroll
        for (int o = 1; o < 8; o <<= 1) {
            int y = __shfl_up_sync(0xFFFFFFFFu, s, o);
            if (lane >= o) s += y;
        }
        ws[lane] = s;
    }
    __syncthreads();
    int incl = x + (wid > 0 ? ws[wid - 1] : 0);
    if (tid < nblocks) g_part[tid] = incl - v;
    if (tid == nblocks - 1) g_ptr[n] = incl;
}

// scan stage C: intra-block exclusive scan + block offset -> g_ptr
__global__ void scanC_kernel(int n) {
    int i = blockIdx.x * blockDim.x + threadIdx.x;
    int lane = threadIdx.x & 31, wid = threadIdx.x >> 5;
    __shared__ int ws[SCAN_TPB / 32];
    int v = (i < n) ? g_deg[i] : 0;
    int x = v;
    #pragma unroll
    for (int o = 1; o < 32; o <<= 1) {
        int y = __shfl_up_sync(0xFFFFFFFFu, x, o);
        if (lane >= o) x += y;
    }
    if (lane == 31) ws[wid] = x;
    __syncthreads();
    if (wid == 0) {
        int s = (lane < SCAN_TPB / 32) ? ws[lane] : 0;
        #pragma unroll
        for (int o = 1; o < SCAN_TPB / 32; o <<= 1) {
            int y = __shfl_up_sync(0xFFFFFFFFu, s, o);
            if (lane >= o) s += y;
        }
        ws[lane] = s;
    }
    __syncthreads();
    int incl = x + (wid > 0 ? ws[wid - 1] : 0);
    if (i < n) g_ptr[i] = incl - v + g_part[blockIdx.x];
}

__global__ void scatter_kernel(const int* __restrict__ ei, int E, int n) {
    int e = blockIdx.x * blockDim.x + threadIdx.x;
    if (e < E) {
        int r = clampN(ei[e], n);
        int c = clampN(ei[E + e], n);
        int pos = g_ptr[c] + atomicAdd(&g_cursor[c], 1);
        float w = g_dinv[r] * g_dinv[c];
        __half2 wh = __floats2half2_rn(w, w);       // pre-packed half2 weight
        g_csr[pos] = make_int2(r, (int)*(unsigned int*)&wh);
    }
}

// ---------------- fused MLP encode: warp/node, h1 stays in registers ------------
__global__ void mlp_kernel(const float* __restrict__ x,
                           const float* __restrict__ W1,
                           const float* __restrict__ b1,
                           const float* __restrict__ W2,
                           const float* __restrict__ b2, int n) {
    int warp = (blockIdx.x * blockDim.x + threadIdx.x) >> 5;
    int lane = threadIdx.x & 31;
    if (warp >= n) return;
    const float* xr = x + (size_t)warp * FIN;
    unsigned long long acc;
    PACK2(acc, b1[2 * lane], b1[2 * lane + 1]);
    for (int kb = 0; kb < FIN; kb += 32) {
        float xv = xr[kb + lane];
        #pragma unroll
        for (int j = 0; j < 32; j++) {
            float xk = __shfl_sync(0xFFFFFFFFu, xv, j);
            unsigned long long xk2, wv;
            PACK2(xk2, xk, xk);
            wv = *(const unsigned long long*)&W1[(kb + j) * FH + 2 * lane];
            FMA2(acc, xk2, wv, acc);
        }
    }
    float a0, a1;
    UNPACK2(a0, a1, acc);
    a0 = fmaxf(a0, 0.0f);                    // h1 feats (2l, 2l+1) in registers
    a1 = fmaxf(a1, 0.0f);

    unsigned long long acc2;
    PACK2(acc2, b2[2 * lane], b2[2 * lane + 1]);
    #pragma unroll
    for (int j = 0; j < 32; j++) {
        float h0j = __shfl_sync(0xFFFFFFFFu, a0, j);   // h1 feat 2j
        float h1j = __shfl_sync(0xFFFFFFFFu, a1, j);   // h1 feat 2j+1
        unsigned long long hp0, hp1, wv0, wv1;
        PACK2(hp0, h0j, h0j);
        PACK2(hp1, h1j, h1j);
        wv0 = *(const unsigned long long*)&W2[(2 * j) * FH + 2 * lane];
        wv1 = *(const unsigned long long*)&W2[(2 * j + 1) * FH + 2 * lane];
        FMA2(acc2, hp0, wv0, acc2);
        FMA2(acc2, hp1, wv1, acc2);
    }
    float c0, c1;
    UNPACK2(c0, c1, acc2);
    g_hA[warp * 32 + lane] = __floats2half2_rn(c0, c1);   // features (2l, 2l+1)
    g_h0[warp * 32 + lane] = make_float2(c0, c1);
}

// ---------------- APPNP step: warp/node, hfma2 groups flushed to fp32 ----------
template <int SRC_A, int DECODE>
__global__ void prop_kernel(const float* __restrict__ Wf,
                            const float* __restrict__ bf,
                            float* __restrict__ out, int n) {
    int node = (blockIdx.x * blockDim.x + threadIdx.x) >> 5;
    int lane = threadIdx.x & 31;
    if (node >= n) return;
    const __half2* __restrict__ hin  = SRC_A ? g_hA : g_hB;
    __half2*       __restrict__ hout = SRC_A ? g_hB : g_hA;

    int start = g_ptr[node];
    int end   = g_ptr[node + 1];

    float di = g_dinv[node];
    float wself = di * di;
    float2 hv = __half22float2(hin[node * 32 + lane]);
    float ax = wself * hv.x;
    float ay = wself * hv.y;

    int e = start;
    for (; e + 4 <= end; e += 4) {
        int2 s0 = g_csr[e + 0];          // uniform (broadcast) loads
        int2 s1 = g_csr[e + 1];
        int2 s2 = g_csr[e + 2];
        int2 s3 = g_csr[e + 3];
        __half2 v0 = hin[s0.x * 32 + lane];  // 4 independent gathers in flight
        __half2 v1 = hin[s1.x * 32 + lane];
        __half2 v2 = hin[s2.x * 32 + lane];
        __half2 v3 = hin[s3.x * 32 + lane];
        __half2 w0 = *(__half2*)&s0.y;
        __half2 w1 = *(__half2*)&s1.y;
        __half2 w2 = *(__half2*)&s2.y;
        __half2 w3 = *(__half2*)&s3.y;
        // fp16 partial over 4 terms, flushed to fp32 (bounded rounding)
        __half2 p = __hmul2(w0, v0);
        p = __hfma2(w1, v1, p);
        p = __hfma2(w2, v2, p);
        p = __hfma2(w3, v3, p);
        float2 fp = __half22float2(p);
        ax += fp.x;
        ay += fp.y;
    }
    for (; e < end; e++) {
        int2 s = g_csr[e];
        float2 f = __half22float2(hin[s.x * 32 + lane]);
        float w = __low2float(*(__half2*)&s.y);
        ax = fmaf(w, f.x, ax);
        ay = fmaf(w, f.y, ay);
    }

    float2 t = g_h0[node * 32 + lane];
    float ox = 0.9f * ax + 0.1f * t.x;     // features (2l, 2l+1), fp32
    float oy = 0.9f * ay + 0.1f * t.y;

    if (!DECODE) {
        hout[node * 32 + lane] = __floats2half2_rn(ox, oy);
    } else {
        // fused decode: out[node] = h @ Wf + bf (h in registers, fp32)
        float acc0 = bf[lane];
        float acc1 = (lane < FOUT - 32) ? bf[lane + 32] : 0.0f;
        #pragma unroll
        for (int j = 0; j < 32; j++) {
            float hx = __shfl_sync(0xFFFFFFFFu, ox, j);   // feature 2j
            float hy = __shfl_sync(0xFFFFFFFFu, oy, j);   // feature 2j+1
            acc0 = fmaf(hx, Wf[(2 * j) * FOUT + lane], acc0);
            acc0 = fmaf(hy, Wf[(2 * j + 1) * FOUT + lane], acc0);
            if (lane < FOUT - 32) {
                acc1 = fmaf(hx, Wf[(2 * j) * FOUT + lane + 32], acc1);
                acc1 = fmaf(hy, Wf[(2 * j + 1) * FOUT + lane + 32], acc1);
            }
        }
        out[(size_t)node * FOUT + lane] = acc0;
        if (lane < FOUT - 32)
            out[(size_t)node * FOUT + lane + 32] = acc1;
    }
}

// ---------------- launch ----------------
extern "C" void kernel_launch(void* const* d_in, const int* in_sizes, int n_in,
                              void* d_out, int out_size) {
    const float* x  = (const float*)d_in[0];
    const int*   ei = (const int*)d_in[1];
    const float* W1 = (const float*)d_in[2];
    const float* b1 = (const float*)d_in[3];
    const float* W2 = (const float*)d_in[4];
    const float* b2 = (const float*)d_in[5];
    const float* Wf = (const float*)d_in[6];
    const float* bf = (const float*)d_in[7];
    float* out = (float*)d_out;

    int N = in_sizes[0] / FIN;
    int E = in_sizes[1] / 2;
    if (N > MAXN) N = MAXN;
    if (E > MAXE) E = MAXE;

    int tpb = 256;
    int nblk = (N + SCAN_TPB - 1) / SCAN_TPB;

    // zero deg + cursor via memset (replaces init_kernel)
    void* deg_addr = nullptr;
    void* cur_addr = nullptr;
    cudaGetSymbolAddress(&deg_addr, g_deg);
    cudaGetSymbolAddress(&cur_addr, g_cursor);
    cudaMemsetAsync(deg_addr, 0, (size_t)N * sizeof(int));
    cudaMemsetAsync(cur_addr, 0, (size_t)N * sizeof(int));

    hist_kernel<<<(E + tpb - 1) / tpb, tpb>>>(ei, E, N);
    scanA_kernel<<<nblk, SCAN_TPB>>>(N);          // also computes dinv
    scanB_kernel<<<1, MAXBLK>>>(nblk, N);
    scanC_kernel<<<nblk, SCAN_TPB>>>(N);
    scatter_kernel<<<(E + tpb - 1) / tpb, tpb>>>(ei, E, N);

    int wblocks = (N + 7) / 8;                 // 8 warps / 256-thread block
    mlp_kernel<<<wblocks, tpb>>>(x, W1, b1, W2, b2, N);   // fused mlp1+mlp2

    // steps 0..8 normal; step 9 (reads B) fuses the decode
    for (int t = 0; t < KSTEPS - 1; t++) {
        if ((t & 1) == 0) prop_kernel<1, 0><<<wblocks, tpb>>>(Wf, bf, out, N);
        else              prop_kernel<0, 0><<<wblocks, tpb>>>(Wf, bf, out, N);
    }
    prop_kernel<0, 1><<<wblocks, tpb>>>(Wf, bf, out, N);
}

// round 13
// speedup vs baseline: 1.1391x; 1.0027x over previous
#include <cuda_runtime.h>
#include <cuda_fp16.h>
#include <cstdint>

#define MAXN 50000
#define MAXE 800000
#define FIN 256
#define FH  64
#define FOUT 40
#define KSTEPS 10
#define SCAN_TPB 256
#define MAXBLK 256

// packed fp32x2 helpers (Blackwell dual fp32)
#define PACK2(out, lo, hi) asm("mov.b64 %0, {%1, %2};" : "=l"(out) : "f"(lo), "f"(hi))
#define UNPACK2(lo, hi, in) asm("mov.b64 {%0, %1}, %2;" : "=f"(lo), "=f"(hi) : "l"(in))
#define FMA2(d, a, b, c) asm("fma.rn.f32x2 %0, %1, %2, %3;" : "=l"(d) : "l"(a), "l"(b), "l"(c))

// ---------------- static device scratch ----------------
__device__ int     g_deg[MAXN];          // raw in-degree, memset to 0 each call
__device__ float   g_dinv[MAXN];
__device__ int     g_ptr[MAXN + 1];
__device__ int     g_cursor[MAXN];       // zeroed in scanA
__device__ int     g_part[MAXBLK];
// csr entry: x = src node, y = fp32 weight bits
__device__ __align__(16) int2    g_csr[MAXE];
// feature pairing: slot p of a node = features (2p, 2p+1); 128B rows, line-aligned
__device__ __align__(256) __half2 g_h0[MAXN * 32];
__device__ __align__(256) __half2 g_hA[MAXN * 32];
__device__ __align__(256) __half2 g_hB[MAXN * 32];

__device__ __forceinline__ int clampN(int v, int n) {
    v = v < 0 ? 0 : v;
    return v >= n ? n - 1 : v;
}

// ---------------- graph preprocessing ----------------
__global__ void hist_kernel(const int* __restrict__ ei, int E, int n) {
    int e = blockIdx.x * blockDim.x + threadIdx.x;
    if (e < E) atomicAdd(&g_deg[clampN(ei[E + e], n)], 1);
}

// scan stage A: per-block sums of raw deg; dinv; cursor zero
__global__ void scanA_kernel(int n) {
    int i = blockIdx.x * blockDim.x + threadIdx.x;
    int lane = threadIdx.x & 31, wid = threadIdx.x >> 5;
    __shared__ int ws[SCAN_TPB / 32];
    int draw = (i < n) ? g_deg[i] : 0;
    if (i < n) {
        g_dinv[i] = rsqrtf((float)(draw + 1));   // self loop included
        g_cursor[i] = 0;
    }
    int v = (i < n) ? draw : 0;
    #pragma unroll
    for (int o = 16; o > 0; o >>= 1) v += __shfl_down_sync(0xFFFFFFFFu, v, o);
    if (lane == 0) ws[wid] = v;
    __syncthreads();
    if (wid == 0) {
        int s = (lane < SCAN_TPB / 32) ? ws[lane] : 0;
        #pragma unroll
        for (int o = 16; o > 0; o >>= 1) s += __shfl_down_sync(0xFFFFFFFFu, s, o);
        if (lane == 0) g_part[blockIdx.x] = s;
    }
}

// scan stage C: prefix of block partials computed in-block (196 partials only),
// then intra-block exclusive scan + offset -> g_ptr. Replaces scanB+scanC.
__global__ void scanC_kernel(int n) {
    int i = blockIdx.x * blockDim.x + threadIdx.x;
    int lane = threadIdx.x & 31, wid = threadIdx.x >> 5;
    __shared__ int ws[SCAN_TPB / 32];
    __shared__ int s_off;

    // block offset = sum of partials of preceding blocks
    {
        int p = 0;
        for (int b = threadIdx.x; b < blockIdx.x; b += blockDim.x) p += g_part[b];
        #pragma unroll
        for (int o = 16; o > 0; o >>= 1) p += __shfl_down_sync(0xFFFFFFFFu, p, o);
        if (lane == 0) ws[wid] = p;
        __syncthreads();
        if (wid == 0) {
            int s = (lane < SCAN_TPB / 32) ? ws[lane] : 0;
            #pragma unroll
            for (int o = 16; o > 0; o >>= 1) s += __shfl_down_sync(0xFFFFFFFFu, s, o);
            if (lane == 0) s_off = s;
        }
        __syncthreads();
    }
    int off = s_off;
    __syncthreads();   // ws reused below

    int v = (i < n) ? g_deg[i] : 0;
    int x = v;
    #pragma unroll
    for (int o = 1; o < 32; o <<= 1) {
        int y = __shfl_up_sync(0xFFFFFFFFu, x, o);
        if (lane >= o) x += y;
    }
    if (lane == 31) ws[wid] = x;
    __syncthreads();
    if (wid == 0) {
        int s = (lane < SCAN_TPB / 32) ? ws[lane] : 0;
        #pragma unroll
        for (int o = 1; o < SCAN_TPB / 32; o <<= 1) {
            int y = __shfl_up_sync(0xFFFFFFFFu, s, o);
            if (lane >= o) s += y;
        }
        ws[lane] = s;
    }
    __syncthreads();
    int incl = x + (wid > 0 ? ws[wid - 1] : 0);
    if (i < n) g_ptr[i] = incl - v + off;
    if (i == n - 1) g_ptr[n] = incl + off;    // total
}

__global__ void scatter_kernel(const int* __restrict__ ei, int E, int n) {
    int e = blockIdx.x * blockDim.x + threadIdx.x;
    if (e < E) {
        int r = clampN(ei[e], n);
        int c = clampN(ei[E + e], n);
        int pos = g_ptr[c] + atomicAdd(&g_cursor[c], 1);
        float w = g_dinv[r] * g_dinv[c];
        g_csr[pos] = make_int2(r, __float_as_int(w));
    }
}

// ---------------- fused MLP encode: warp/node, h1 stays in registers ------------
__global__ void mlp_kernel(const float* __restrict__ x,
                           const float* __restrict__ W1,
                           const float* __restrict__ b1,
                           const float* __restrict__ W2,
                           const float* __restrict__ b2, int n) {
    int warp = (blockIdx.x * blockDim.x + threadIdx.x) >> 5;
    int lane = threadIdx.x & 31;
    if (warp >= n) return;
    const float* xr = x + (size_t)warp * FIN;
    unsigned long long acc;
    PACK2(acc, b1[2 * lane], b1[2 * lane + 1]);
    for (int kb = 0; kb < FIN; kb += 32) {
        float xv = xr[kb + lane];
        #pragma unroll
        for (int j = 0; j < 32; j++) {
            float xk = __shfl_sync(0xFFFFFFFFu, xv, j);
            unsigned long long xk2, wv;
            PACK2(xk2, xk, xk);
            wv = *(const unsigned long long*)&W1[(kb + j) * FH + 2 * lane];
            FMA2(acc, xk2, wv, acc);
        }
    }
    float a0, a1;
    UNPACK2(a0, a1, acc);
    a0 = fmaxf(a0, 0.0f);                    // h1 feats (2l, 2l+1) in registers
    a1 = fmaxf(a1, 0.0f);

    unsigned long long acc2;
    PACK2(acc2, b2[2 * lane], b2[2 * lane + 1]);
    #pragma unroll
    for (int j = 0; j < 32; j++) {
        float h0j = __shfl_sync(0xFFFFFFFFu, a0, j);   // h1 feat 2j
        float h1j = __shfl_sync(0xFFFFFFFFu, a1, j);   // h1 feat 2j+1
        unsigned long long hp0, hp1, wv0, wv1;
        PACK2(hp0, h0j, h0j);
        PACK2(hp1, h1j, h1j);
        wv0 = *(const unsigned long long*)&W2[(2 * j) * FH + 2 * lane];
        wv1 = *(const unsigned long long*)&W2[(2 * j + 1) * FH + 2 * lane];
        FMA2(acc2, hp0, wv0, acc2);
        FMA2(acc2, hp1, wv1, acc2);
    }
    float c0, c1;
    UNPACK2(c0, c1, acc2);
    __half2 hpair = __floats2half2_rn(c0, c1);      // features (2l, 2l+1)
    g_hA[warp * 32 + lane] = hpair;
    g_h0[warp * 32 + lane] = hpair;                 // h0 now half2 too
}

// ---------------- APPNP step: warp/node, fp32 fmaf, unroll x4 ------------------
template <int SRC_A, int DECODE>
__global__ void prop_kernel(const float* __restrict__ Wf,
                            const float* __restrict__ bf,
                            float* __restrict__ out, int n) {
    int node = (blockIdx.x * blockDim.x + threadIdx.x) >> 5;
    int lane = threadIdx.x & 31;
    if (node >= n) return;
    const __half2* __restrict__ hin  = SRC_A ? g_hA : g_hB;
    __half2*       __restrict__ hout = SRC_A ? g_hB : g_hA;

    int start = g_ptr[node];
    int end   = g_ptr[node + 1];

    float di = g_dinv[node];
    float wself = di * di;
    float2 hv = __half22float2(hin[node * 32 + lane]);
    float ax = wself * hv.x;
    float ay = wself * hv.y;

    int e = start;
    for (; e + 4 <= end; e += 4) {
        int2 s0 = g_csr[e + 0];          // uniform (broadcast) loads
        int2 s1 = g_csr[e + 1];
        int2 s2 = g_csr[e + 2];
        int2 s3 = g_csr[e + 3];
        __half2 v0 = hin[s0.x * 32 + lane];  // 4 independent gathers in flight
        __half2 v1 = hin[s1.x * 32 + lane];
        __half2 v2 = hin[s2.x * 32 + lane];
        __half2 v3 = hin[s3.x * 32 + lane];
        float2 f0 = __half22float2(v0);
        float2 f1 = __half22float2(v1);
        float2 f2 = __half22float2(v2);
        float2 f3 = __half22float2(v3);
        float w0 = __int_as_float(s0.y);
        float w1 = __int_as_float(s1.y);
        float w2 = __int_as_float(s2.y);
        float w3 = __int_as_float(s3.y);
        ax = fmaf(w0, f0.x, ax);  ay = fmaf(w0, f0.y, ay);
        ax = fmaf(w1, f1.x, ax);  ay = fmaf(w1, f1.y, ay);
        ax = fmaf(w2, f2.x, ax);  ay = fmaf(w2, f2.y, ay);
        ax = fmaf(w3, f3.x, ax);  ay = fmaf(w3, f3.y, ay);
    }
    for (; e < end; e++) {
        int2 s = g_csr[e];
        float2 f = __half22float2(hin[s.x * 32 + lane]);
        float w = __int_as_float(s.y);
        ax = fmaf(w, f.x, ax);
        ay = fmaf(w, f.y, ay);
    }

    float2 t = __half22float2(g_h0[node * 32 + lane]);
    float ox = 0.9f * ax + 0.1f * t.x;     // features (2l, 2l+1), fp32
    float oy = 0.9f * ay + 0.1f * t.y;

    if (!DECODE) {
        hout[node * 32 + lane] = __floats2half2_rn(ox, oy);
    } else {
        // fused decode: out[node] = h @ Wf + bf (h in registers, fp32)
        float acc0 = bf[lane];
        float acc1 = (lane < FOUT - 32) ? bf[lane + 32] : 0.0f;
        #pragma unroll
        for (int j = 0; j < 32; j++) {
            float hx = __shfl_sync(0xFFFFFFFFu, ox, j);   // feature 2j
            float hy = __shfl_sync(0xFFFFFFFFu, oy, j);   // feature 2j+1
            acc0 = fmaf(hx, Wf[(2 * j) * FOUT + lane], acc0);
            acc0 = fmaf(hy, Wf[(2 * j + 1) * FOUT + lane], acc0);
            if (lane < FOUT - 32) {
                acc1 = fmaf(hx, Wf[(2 * j) * FOUT + lane + 32], acc1);
                acc1 = fmaf(hy, Wf[(2 * j + 1) * FOUT + lane + 32], acc1);
            }
        }
        out[(size_t)node * FOUT + lane] = acc0;
        if (lane < FOUT - 32)
            out[(size_t)node * FOUT + lane + 32] = acc1;
    }
}

// ---------------- launch ----------------
extern "C" void kernel_launch(void* const* d_in, const int* in_sizes, int n_in,
                              void* d_out, int out_size) {
    const float* x  = (const float*)d_in[0];
    const int*   ei = (const int*)d_in[1];
    const float* W1 = (const float*)d_in[2];
    const float* b1 = (const float*)d_in[3];
    const float* W2 = (const float*)d_in[4];
    const float* b2 = (const float*)d_in[5];
    const float* Wf = (const float*)d_in[6];
    const float* bf = (const float*)d_in[7];
    float* out = (float*)d_out;

    int N = in_sizes[0] / FIN;
    int E = in_sizes[1] / 2;
    if (N > MAXN) N = MAXN;
    if (E > MAXE) E = MAXE;

    int tpb = 256;
    int nblk = (N + SCAN_TPB - 1) / SCAN_TPB;

    void* deg_addr = nullptr;
    cudaGetSymbolAddress(&deg_addr, g_deg);
    cudaMemsetAsync(deg_addr, 0, (size_t)N * sizeof(int));

    hist_kernel<<<(E + tpb - 1) / tpb, tpb>>>(ei, E, N);
    scanA_kernel<<<nblk, SCAN_TPB>>>(N);          // partials + dinv + cursor=0
    scanC_kernel<<<nblk, SCAN_TPB>>>(N);          // replaces scanB+scanC
    scatter_kernel<<<(E + tpb - 1) / tpb, tpb>>>(ei, E, N);

    int wblocks = (N + 7) / 8;                 // 8 warps / 256-thread block
    mlp_kernel<<<wblocks, tpb>>>(x, W1, b1, W2, b2, N);   // fused mlp1+mlp2

    // steps 0..8 normal; step 9 (reads B) fuses the decode
    for (int t = 0; t < KSTEPS - 1; t++) {
        if ((t & 1) == 0) prop_kernel<1, 0><<<wblocks, tpb>>>(Wf, bf, out, N);
        else              prop_kernel<0, 0><<<wblocks, tpb>>>(Wf, bf, out, N);
    }
    prop_kernel<0, 1><<<wblocks, tpb>>>(Wf, bf, out, N);
}